// round 2
// baseline (speedup 1.0000x reference)
#include <cuda_runtime.h>
#include <math.h>

#define B_  64
#define T_  1024
#define I_  512
#define H_  1024

// ---------------- f32x2 (packed fp32) helpers — IEEE-exact, 2x FFMA rate ----
__device__ __forceinline__ unsigned long long f2fma(unsigned long long a,
                                                    unsigned long long b,
                                                    unsigned long long c) {
    unsigned long long d;
    asm("fma.rn.f32x2 %0, %1, %2, %3;" : "=l"(d) : "l"(a), "l"(b), "l"(c));
    return d;
}
__device__ __forceinline__ unsigned long long f2dup(float x) {
    unsigned long long d;
    asm("mov.b64 %0, {%1, %1};" : "=l"(d) : "f"(x));
    return d;
}
__device__ __forceinline__ float2 f2unpack(unsigned long long v) {
    float2 r;
    asm("mov.b64 {%0, %1}, %2;" : "=f"(r.x), "=f"(r.y) : "l"(v));
    return r;
}

// ---------------- global scratch (no allocations allowed) -------------------
__device__ float    g_h[2][B_ * H_];   // double-buffered hidden state
__device__ unsigned g_bar;             // monotonic grid barrier counter

// ---------------- init: zero h0 and barrier ---------------------------------
__global__ void init_kernel() {
    int idx = blockIdx.x * blockDim.x + threadIdx.x;
    for (int i = idx; i < B_ * H_; i += gridDim.x * blockDim.x)
        g_h[0][i] = 0.0f;
    if (idx == 0) g_bar = 0u;
}

// ---------------- Phase 1: xp = x @ input_w + b  (written into d_out) -------
#define PTM 128
#define PTN 64
#define PTK 32
#define ASTR 132   // padded strides to avoid STS bank conflicts
#define BSTR 68

__global__ void __launch_bounds__(256)
proj_kernel(const float* __restrict__ x, const float* __restrict__ wi,
            const float* __restrict__ bias, float* __restrict__ out) {
    __shared__ float As[PTK * ASTR];
    __shared__ float Bs[PTK * BSTR];
    const int tid = threadIdx.x;
    const int m0 = blockIdx.y * PTM;
    const int n0 = blockIdx.x * PTN;
    const int ty = tid >> 4;    // 0..15 -> 8 rows each
    const int tx = tid & 15;    // 0..15 -> 4 cols each

    unsigned long long acc[8][2];
#pragma unroll
    for (int i = 0; i < 8; ++i) { acc[i][0] = 0ull; acc[i][1] = 0ull; }

    for (int kt = 0; kt < I_ / PTK; ++kt) {
        const int k0 = kt * PTK;
        // load A tile (transposed into [k][m])
#pragma unroll
        for (int i = 0; i < 4; ++i) {
            int idx = tid + i * 256;               // 0..1023
            int row = idx >> 3;
            int kl  = (idx & 7) << 2;
            float4 v = *(const float4*)(x + (size_t)(m0 + row) * I_ + k0 + kl);
            As[(kl + 0) * ASTR + row] = v.x;
            As[(kl + 1) * ASTR + row] = v.y;
            As[(kl + 2) * ASTR + row] = v.z;
            As[(kl + 3) * ASTR + row] = v.w;
        }
        // load B tile [k][n]
#pragma unroll
        for (int i = 0; i < 2; ++i) {
            int idx = tid + i * 256;               // 0..511
            int kr  = idx >> 4;
            int c4  = (idx & 15) << 2;
            float4 v = *(const float4*)(wi + (size_t)(k0 + kr) * H_ + n0 + c4);
            *(float4*)&Bs[kr * BSTR + c4] = v;
        }
        __syncthreads();
#pragma unroll
        for (int k = 0; k < PTK; ++k) {
            float a[8];
            *(float4*)&a[0] = *(const float4*)&As[k * ASTR + ty * 8];
            *(float4*)&a[4] = *(const float4*)&As[k * ASTR + ty * 8 + 4];
            ulonglong2 bv = *(const ulonglong2*)&Bs[k * BSTR + tx * 4];
#pragma unroll
            for (int i = 0; i < 8; ++i) {
                unsigned long long ad = f2dup(a[i]);
                acc[i][0] = f2fma(ad, bv.x, acc[i][0]);
                acc[i][1] = f2fma(ad, bv.y, acc[i][1]);
            }
        }
        __syncthreads();
    }
    float4 bb = *(const float4*)(bias + n0 + tx * 4);
#pragma unroll
    for (int i = 0; i < 8; ++i) {
        float2 lo = f2unpack(acc[i][0]);
        float2 hi = f2unpack(acc[i][1]);
        float4 o;
        o.x = lo.x + bb.x; o.y = lo.y + bb.y;
        o.z = hi.x + bb.z; o.w = hi.y + bb.w;
        *(float4*)(out + (size_t)(m0 + ty * 8 + i) * H_ + n0 + tx * 4) = o;
    }
}

// ---------------- Phase 2: persistent recurrent kernel ----------------------
// 128 CTAs (1/SM, co-resident): tile = 16 batch rows x 32 H columns.
// W slice lives in SMEM for all 1024 steps. h exchanged via L2 + grid barrier.
#define RGRID    128
#define RTHREADS 128
#define BT 16
#define NT 32
#define HPAD (H_ + 8)
#define W_S_FLOATS (H_ * NT)
#define H_S_FLOATS (BT * HPAD)
#define RNN_SMEM_BYTES ((W_S_FLOATS + H_S_FLOATS) * 4)

__global__ void __launch_bounds__(RTHREADS, 1)
rnn_kernel(const float* __restrict__ W, float* __restrict__ out) {
    extern __shared__ float smem[];
    float* w_s = smem;                 // [H_][NT]
    float* h_s = smem + W_S_FLOATS;    // [BT][HPAD]

    const int tid = threadIdx.x;
    const int bt  = blockIdx.x >> 5;   // 0..3   (batch tile)
    const int nt  = blockIdx.x & 31;   // 0..31  (column tile)
    const int b0  = bt * BT;
    const int n0  = nt * NT;
    const int b   = tid >> 3;          // 0..15 local batch row
    const int nq  = tid & 7;           // 0..7  -> 4 cols each

    // Cache W[:, n0:n0+32] in SMEM once (reused for all 1024 steps).
    for (int i = tid; i < W_S_FLOATS / 4; i += RTHREADS) {
        int k  = i >> 3;               // 0..1023
        int j4 = (i & 7) << 2;         // 0,4,...,28
        float4 v = *(const float4*)(W + (size_t)k * H_ + n0 + j4);
        *(float4*)&w_s[k * NT + j4] = v;
    }
    __syncthreads();

    const float* wcol = &w_s[nq * 4];

    for (int t = 0; t < T_; ++t) {
        // Stage h_prev[b0:b0+16, :] from L2 into SMEM (bypass L1: cross-SM data)
        const float* hsrc = g_h[t & 1] + b0 * H_;
        for (int i = tid; i < (BT * H_) / 4; i += RTHREADS) {
            int r  = i >> 8;           // 0..15
            int c4 = (i & 255) << 2;   // 0..1020
            float4 v = __ldcg((const float4*)(hsrc + r * H_ + c4));
            *(float4*)&h_s[r * HPAD + c4] = v;
        }
        __syncthreads();

        unsigned long long acc0 = 0ull, acc1 = 0ull;
        const float* hrow = &h_s[b * HPAD];
#pragma unroll 4
        for (int k = 0; k < H_; k += 4) {
            float4 hv = *(const float4*)&hrow[k];
            {
                ulonglong2 wv = *(const ulonglong2*)&wcol[(k + 0) * NT];
                unsigned long long hd = f2dup(hv.x);
                acc0 = f2fma(hd, wv.x, acc0);
                acc1 = f2fma(hd, wv.y, acc1);
            }
            {
                ulonglong2 wv = *(const ulonglong2*)&wcol[(k + 1) * NT];
                unsigned long long hd = f2dup(hv.y);
                acc0 = f2fma(hd, wv.x, acc0);
                acc1 = f2fma(hd, wv.y, acc1);
            }
            {
                ulonglong2 wv = *(const ulonglong2*)&wcol[(k + 2) * NT];
                unsigned long long hd = f2dup(hv.z);
                acc0 = f2fma(hd, wv.x, acc0);
                acc1 = f2fma(hd, wv.y, acc1);
            }
            {
                ulonglong2 wv = *(const ulonglong2*)&wcol[(k + 3) * NT];
                unsigned long long hd = f2dup(hv.w);
                acc0 = f2fma(hd, wv.x, acc0);
                acc1 = f2fma(hd, wv.y, acc1);
            }
        }

        float2 a0 = f2unpack(acc0);
        float2 a1 = f2unpack(acc1);
        // xp was pre-stored in d_out; read it, overwrite with h_t (same owner).
        size_t obase = ((size_t)(b0 + b) * T_ + t) * H_ + n0 + nq * 4;
        float4 xv = *(const float4*)(out + obase);
        float4 hn;
        hn.x = tanhf(a0.x + xv.x);
        hn.y = tanhf(a0.y + xv.y);
        hn.z = tanhf(a1.x + xv.z);
        hn.w = tanhf(a1.y + xv.w);
        *(float4*)(out + obase) = hn;
        *(float4*)&g_h[(t + 1) & 1][(size_t)(b0 + b) * H_ + n0 + nq * 4] = hn;

        // Grid barrier (monotonic counter; release on writer, acquire on reader)
        __syncthreads();
        if (tid == 0) {
            __threadfence();
            atomicAdd(&g_bar, 1u);
            const unsigned target = (unsigned)gridDim.x * (unsigned)(t + 1);
            unsigned v;
            do {
                asm volatile("ld.global.acquire.gpu.u32 %0, [%1];"
                             : "=r"(v) : "l"(&g_bar));
            } while (v < target);
        }
        __syncthreads();
    }
}

// ---------------- launch ----------------------------------------------------
extern "C" void kernel_launch(void* const* d_in, const int* in_sizes, int n_in,
                              void* d_out, int out_size) {
    const float *x = nullptr, *hw = nullptr, *iw = nullptr, *bias = nullptr;
    for (int i = 0; i < n_in; ++i) {
        long long s = in_sizes[i];
        if      (s == (long long)B_ * T_ * I_) x    = (const float*)d_in[i];
        else if (s == (long long)H_ * H_)      hw   = (const float*)d_in[i];
        else if (s == (long long)I_ * H_)      iw   = (const float*)d_in[i];
        else if (s == (long long)H_)           bias = (const float*)d_in[i];
    }
    float* out = (float*)d_out;

    cudaFuncSetAttribute(rnn_kernel,
                         cudaFuncAttributeMaxDynamicSharedMemorySize,
                         RNN_SMEM_BYTES);

    dim3 pgrid(H_ / PTN, (B_ * T_) / PTM);   // (16, 512)
    proj_kernel<<<pgrid, 256>>>(x, iw, bias, out);
    init_kernel<<<64, 256>>>();
    rnn_kernel<<<RGRID, RTHREADS, RNN_SMEM_BYTES>>>(hw, out);
}

// round 4
// speedup vs baseline: 1.5256x; 1.5256x over previous
#include <cuda_runtime.h>
#include <math.h>

#define B_  64
#define T_  1024
#define I_  512
#define H_  1024

// ---------------- f32x2 (packed fp32) helpers — IEEE-exact, 2x FFMA rate ----
__device__ __forceinline__ unsigned long long f2fma(unsigned long long a,
                                                    unsigned long long b,
                                                    unsigned long long c) {
    unsigned long long d;
    asm("fma.rn.f32x2 %0, %1, %2, %3;" : "=l"(d) : "l"(a), "l"(b), "l"(c));
    return d;
}
__device__ __forceinline__ unsigned long long f2add(unsigned long long a,
                                                    unsigned long long b) {
    unsigned long long d;
    asm("add.rn.f32x2 %0, %1, %2;" : "=l"(d) : "l"(a), "l"(b));
    return d;
}
__device__ __forceinline__ unsigned long long f2dup(float x) {
    unsigned long long d;
    asm("mov.b64 %0, {%1, %1};" : "=l"(d) : "f"(x));
    return d;
}
__device__ __forceinline__ float2 f2unpack(unsigned long long v) {
    float2 r;
    asm("mov.b64 {%0, %1}, %2;" : "=f"(r.x), "=f"(r.y) : "l"(v));
    return r;
}

// ---------------- global scratch (no allocations allowed) -------------------
__device__ float    g_h[2][B_ * H_];   // double-buffered hidden state
__device__ unsigned g_bar4[4];         // per-bt-group monotonic barrier

// ---------------- init: zero h0 and barriers --------------------------------
__global__ void init_kernel() {
    int idx = blockIdx.x * blockDim.x + threadIdx.x;
    for (int i = idx; i < B_ * H_; i += gridDim.x * blockDim.x)
        g_h[0][i] = 0.0f;
    if (idx < 4) g_bar4[idx] = 0u;
}

// ---------------- Phase 1: xp = x @ input_w + b  (written into d_out) -------
#define PTM 128
#define PTN 64
#define PTK 32
#define ASTR 132
#define BSTR 68

__global__ void __launch_bounds__(256)
proj_kernel(const float* __restrict__ x, const float* __restrict__ wi,
            const float* __restrict__ bias, float* __restrict__ out) {
    __shared__ float As[PTK * ASTR];
    __shared__ float Bs[PTK * BSTR];
    const int tid = threadIdx.x;
    const int m0 = blockIdx.y * PTM;
    const int n0 = blockIdx.x * PTN;
    const int ty = tid >> 4;
    const int tx = tid & 15;

    unsigned long long acc[8][2];
#pragma unroll
    for (int i = 0; i < 8; ++i) { acc[i][0] = 0ull; acc[i][1] = 0ull; }

    for (int kt = 0; kt < I_ / PTK; ++kt) {
        const int k0 = kt * PTK;
#pragma unroll
        for (int i = 0; i < 4; ++i) {
            int idx = tid + i * 256;
            int row = idx >> 3;
            int kl  = (idx & 7) << 2;
            float4 v = *(const float4*)(x + (size_t)(m0 + row) * I_ + k0 + kl);
            As[(kl + 0) * ASTR + row] = v.x;
            As[(kl + 1) * ASTR + row] = v.y;
            As[(kl + 2) * ASTR + row] = v.z;
            As[(kl + 3) * ASTR + row] = v.w;
        }
#pragma unroll
        for (int i = 0; i < 2; ++i) {
            int idx = tid + i * 256;
            int kr  = idx >> 4;
            int c4  = (idx & 15) << 2;
            float4 v = *(const float4*)(wi + (size_t)(k0 + kr) * H_ + n0 + c4);
            *(float4*)&Bs[kr * BSTR + c4] = v;
        }
        __syncthreads();
#pragma unroll
        for (int k = 0; k < PTK; ++k) {
            float a[8];
            *(float4*)&a[0] = *(const float4*)&As[k * ASTR + ty * 8];
            *(float4*)&a[4] = *(const float4*)&As[k * ASTR + ty * 8 + 4];
            ulonglong2 bv = *(const ulonglong2*)&Bs[k * BSTR + tx * 4];
#pragma unroll
            for (int i = 0; i < 8; ++i) {
                unsigned long long ad = f2dup(a[i]);
                acc[i][0] = f2fma(ad, bv.x, acc[i][0]);
                acc[i][1] = f2fma(ad, bv.y, acc[i][1]);
            }
        }
        __syncthreads();
    }
    float4 bb = *(const float4*)(bias + n0 + tx * 4);
#pragma unroll
    for (int i = 0; i < 8; ++i) {
        float2 lo = f2unpack(acc[i][0]);
        float2 hi = f2unpack(acc[i][1]);
        float4 o;
        o.x = lo.x + bb.x; o.y = lo.y + bb.y;
        o.z = hi.x + bb.z; o.w = hi.y + bb.w;
        *(float4*)(out + (size_t)(m0 + ty * 8 + i) * H_ + n0 + tx * 4) = o;
    }
}

// ---------------- Phase 2: persistent recurrent kernel ----------------------
// 128 CTAs (1/SM): tile = 16 batch rows x 32 H cols, 256 threads.
// Thread = 2 rows x 2 cols; K split across two 4-warp groups (SMEM reduce).
// W repacked in SMEM as {w[k][n0],w[k][n1],w[k+1][n0],w[k+1][n1]} per float4.
// h staged row-pair-interleaved: hp[rp][k] = (h[2rp][k], h[2rp+1][k]).
#define RGRID    128
#define RTHREADS 256
#define BT 16
#define NT 32
#define HPSTR 1026                       // float2 units per rowpair (pad: +2)
#define W_S_FLOATS (H_ * NT)             // 32768 floats = 128 KB
#define HP_FLOATS  (8 * HPSTR * 2)       // 16416 floats ≈ 64.1 KB
#define RNN_SMEM_BYTES ((W_S_FLOATS + HP_FLOATS) * 4)

__global__ void __launch_bounds__(RTHREADS, 1)
rnn_kernel(const float* __restrict__ W, float* __restrict__ out) {
    extern __shared__ float smem[];
    float* w_s  = smem;                  // packed W slice [1024 k][32 n]
    float* hp_s = smem + W_S_FLOATS;     // pair-interleaved h tile

    const int tid  = threadIdx.x;
    const int bt   = blockIdx.x >> 5;    // 0..3
    const int nt   = blockIdx.x & 31;    // 0..31
    const int b0   = bt * BT;
    const int n0   = nt * NT;

    const int lane = tid & 31;
    const int wg   = (tid >> 5) & 3;     // warp-in-kgroup
    const int kg   = tid >> 7;           // k-half 0/1
    const int wtid = tid & 127;
    const int rp   = lane & 7;           // rowpair 0..7
    const int cp   = wg * 4 + (lane >> 3); // colpair 0..15

    // ---- one-time: pack W[:, n0:n0+32] into SMEM (reused 1024 steps) ----
    // idx(k,n) = (k>>1)*64 + (n>>1)*4 + (k&1)*2 + (n&1)
    for (int i = tid; i < W_S_FLOATS / 4; i += RTHREADS) {
        int k  = i >> 3;
        int n4 = (i & 7) << 2;
        float4 v = *(const float4*)(W + (size_t)k * H_ + n0 + n4);
        int base = (k >> 1) * 64 + (k & 1) * 2 + (n4 >> 1) * 4;
        w_s[base + 0] = v.x;
        w_s[base + 1] = v.y;
        w_s[base + 4] = v.z;
        w_s[base + 5] = v.w;
    }
    __syncthreads();

    const int R0 = b0 + 2 * rp;
    const int C0 = n0 + 2 * cp;
    const float* wp     = w_s + kg * 16384 + cp * 4;
    const float* hpbase = hp_s + ((size_t)rp * HPSTR + kg * 512) * 2;

    for (int t = 0; t < T_; ++t) {
        // ---- prefetch xp (independent of h; DRAM latency hidden by compute)
        float2 xv0 = make_float2(0.f, 0.f), xv1 = xv0;
        size_t ob0 = ((size_t)R0 * T_ + t) * H_ + C0;
        size_t ob1 = ((size_t)(R0 + 1) * T_ + t) * H_ + C0;
        if (kg == 0) {
            xv0 = *(const float2*)(out + ob0);
            xv1 = *(const float2*)(out + ob1);
        }

        // ---- stage h_prev rows (pair-interleaved) from L2 into SMEM ----
        const float* hsrc = g_h[t & 1];
#pragma unroll
        for (int it = 0; it < 8; ++it) {
            int i  = tid + it * 256;         // 0..2047
            int p  = i >> 8;                 // rowpair
            int kc = i & 255;                // float4 chunk along k
            const float* ra = hsrc + (size_t)(b0 + 2 * p) * H_ + kc * 4;
            float4 a = __ldcg((const float4*)ra);
            float4 b = __ldcg((const float4*)(ra + H_));
            float* dst = hp_s + ((size_t)p * HPSTR + kc * 4) * 2;
            *(float4*)dst       = make_float4(a.x, b.x, a.y, b.y);
            *(float4*)(dst + 4) = make_float4(a.z, b.z, a.w, b.w);
        }
        __syncthreads();

        // ---- main FMA loop over this group's K half (512 k) ----
        unsigned long long a0e = 0ull, a0o = 0ull, a1e = 0ull, a1o = 0ull;
#pragma unroll 4
        for (int kk = 0; kk < 512; kk += 2) {
            ulonglong2 wv = *(const ulonglong2*)(wp + (kk >> 1) * 64);
            float4     hv = *(const float4*)(hpbase + kk * 2);
            a0e = f2fma(f2dup(hv.x), wv.x, a0e);  // row0, k
            a1e = f2fma(f2dup(hv.y), wv.x, a1e);  // row1, k
            a0o = f2fma(f2dup(hv.z), wv.y, a0o);  // row0, k+1
            a1o = f2fma(f2dup(hv.w), wv.y, a1o);  // row1, k+1
        }
        unsigned long long accR0 = f2add(a0e, a0o);
        unsigned long long accR1 = f2add(a1e, a1o);

        // ---- cross-kgroup reduction via SMEM (reuse hp_s front) ----
        __syncthreads();
        unsigned long long* red = (unsigned long long*)hp_s;
        if (kg == 1) {
            ulonglong2 pr; pr.x = accR0; pr.y = accR1;
            *(ulonglong2*)(red + wtid * 2) = pr;
        }
        __syncthreads();
        if (kg == 0) {
            ulonglong2 pr = *(const ulonglong2*)(red + wtid * 2);
            accR0 = f2add(accR0, pr.x);
            accR1 = f2add(accR1, pr.y);
            float2 s0 = f2unpack(accR0);
            float2 s1 = f2unpack(accR1);
            float2 h0, h1;
            h0.x = tanhf(s0.x + xv0.x);
            h0.y = tanhf(s0.y + xv0.y);
            h1.x = tanhf(s1.x + xv1.x);
            h1.y = tanhf(s1.y + xv1.y);
            *(float2*)(out + ob0) = h0;
            *(float2*)(out + ob1) = h1;
            float* gdst = g_h[(t + 1) & 1];
            *(float2*)(gdst + (size_t)R0 * H_ + C0)       = h0;
            *(float2*)(gdst + (size_t)(R0 + 1) * H_ + C0) = h1;
        }

        // ---- per-bt-group grid barrier (32 CTAs) ----
        __syncthreads();
        if (tid == 0) {
            unsigned* bar = &g_bar4[bt];
            __threadfence();
            atomicAdd(bar, 1u);
            const unsigned target = 32u * (unsigned)(t + 1);
            unsigned v;
            do {
                asm volatile("ld.global.acquire.gpu.u32 %0, [%1];"
                             : "=r"(v) : "l"(bar));
            } while (v < target);
        }
        __syncthreads();
    }
}

// ---------------- launch ----------------------------------------------------
extern "C" void kernel_launch(void* const* d_in, const int* in_sizes, int n_in,
                              void* d_out, int out_size) {
    const float *x = nullptr, *hw = nullptr, *iw = nullptr, *bias = nullptr;
    for (int i = 0; i < n_in; ++i) {
        long long s = in_sizes[i];
        if      (s == (long long)B_ * T_ * I_) x    = (const float*)d_in[i];
        else if (s == (long long)H_ * H_)      hw   = (const float*)d_in[i];
        else if (s == (long long)I_ * H_)      iw   = (const float*)d_in[i];
        else if (s == (long long)H_)           bias = (const float*)d_in[i];
    }
    float* out = (float*)d_out;

    cudaFuncSetAttribute(rnn_kernel,
                         cudaFuncAttributeMaxDynamicSharedMemorySize,
                         RNN_SMEM_BYTES);

    dim3 pgrid(H_ / PTN, (B_ * T_) / PTM);   // (16, 512)
    proj_kernel<<<pgrid, 256>>>(x, iw, bias, out);
    init_kernel<<<64, 256>>>();
    rnn_kernel<<<RGRID, RTHREADS, RNN_SMEM_BYTES>>>(hw, out);
}

// round 5
// speedup vs baseline: 2.0621x; 1.3517x over previous
#include <cuda_runtime.h>
#include <math.h>

#define B_  64
#define T_  1024
#define I_  512
#define H_  1024

// ---------------- f32x2 (packed fp32) helpers — IEEE-exact, 2x FFMA rate ----
__device__ __forceinline__ unsigned long long f2fma(unsigned long long a,
                                                    unsigned long long b,
                                                    unsigned long long c) {
    unsigned long long d;
    asm("fma.rn.f32x2 %0, %1, %2, %3;" : "=l"(d) : "l"(a), "l"(b), "l"(c));
    return d;
}
__device__ __forceinline__ unsigned long long f2add(unsigned long long a,
                                                    unsigned long long b) {
    unsigned long long d;
    asm("add.rn.f32x2 %0, %1, %2;" : "=l"(d) : "l"(a), "l"(b));
    return d;
}
__device__ __forceinline__ unsigned long long f2dup(float x) {
    unsigned long long d;
    asm("mov.b64 %0, {%1, %1};" : "=l"(d) : "f"(x));
    return d;
}
__device__ __forceinline__ float2 f2unpack(unsigned long long v) {
    float2 r;
    asm("mov.b64 {%0, %1}, %2;" : "=f"(r.x), "=f"(r.y) : "l"(v));
    return r;
}

// ---------------- global scratch (no allocations allowed) -------------------
__device__ float    g_h[2][B_ * H_];   // double-buffered hidden state
__device__ unsigned g_bar4[4];         // per-bt-group monotonic barrier

// ---------------- init: zero h0 and barriers --------------------------------
__global__ void init_kernel() {
    int idx = blockIdx.x * blockDim.x + threadIdx.x;
    for (int i = idx; i < B_ * H_; i += gridDim.x * blockDim.x)
        g_h[0][i] = 0.0f;
    if (idx < 4) g_bar4[idx] = 0u;
}

// ---------------- Phase 1: xp = x @ input_w + b  (written into d_out) -------
#define PTM 128
#define PTN 64
#define PTK 32
#define ASTR 132
#define BSTR 68

__global__ void __launch_bounds__(256)
proj_kernel(const float* __restrict__ x, const float* __restrict__ wi,
            const float* __restrict__ bias, float* __restrict__ out) {
    __shared__ float As[PTK * ASTR];
    __shared__ float Bs[PTK * BSTR];
    const int tid = threadIdx.x;
    const int m0 = blockIdx.y * PTM;
    const int n0 = blockIdx.x * PTN;
    const int ty = tid >> 4;
    const int tx = tid & 15;

    unsigned long long acc[8][2];
#pragma unroll
    for (int i = 0; i < 8; ++i) { acc[i][0] = 0ull; acc[i][1] = 0ull; }

    for (int kt = 0; kt < I_ / PTK; ++kt) {
        const int k0 = kt * PTK;
#pragma unroll
        for (int i = 0; i < 4; ++i) {
            int idx = tid + i * 256;
            int row = idx >> 3;
            int kl  = (idx & 7) << 2;
            float4 v = *(const float4*)(x + (size_t)(m0 + row) * I_ + k0 + kl);
            As[(kl + 0) * ASTR + row] = v.x;
            As[(kl + 1) * ASTR + row] = v.y;
            As[(kl + 2) * ASTR + row] = v.z;
            As[(kl + 3) * ASTR + row] = v.w;
        }
#pragma unroll
        for (int i = 0; i < 2; ++i) {
            int idx = tid + i * 256;
            int kr  = idx >> 4;
            int c4  = (idx & 15) << 2;
            float4 v = *(const float4*)(wi + (size_t)(k0 + kr) * H_ + n0 + c4);
            *(float4*)&Bs[kr * BSTR + c4] = v;
        }
        __syncthreads();
#pragma unroll
        for (int k = 0; k < PTK; ++k) {
            float a[8];
            *(float4*)&a[0] = *(const float4*)&As[k * ASTR + ty * 8];
            *(float4*)&a[4] = *(const float4*)&As[k * ASTR + ty * 8 + 4];
            ulonglong2 bv = *(const ulonglong2*)&Bs[k * BSTR + tx * 4];
#pragma unroll
            for (int i = 0; i < 8; ++i) {
                unsigned long long ad = f2dup(a[i]);
                acc[i][0] = f2fma(ad, bv.x, acc[i][0]);
                acc[i][1] = f2fma(ad, bv.y, acc[i][1]);
            }
        }
        __syncthreads();
    }
    float4 bb = *(const float4*)(bias + n0 + tx * 4);
#pragma unroll
    for (int i = 0; i < 8; ++i) {
        float2 lo = f2unpack(acc[i][0]);
        float2 hi = f2unpack(acc[i][1]);
        float4 o;
        o.x = lo.x + bb.x; o.y = lo.y + bb.y;
        o.z = hi.x + bb.z; o.w = hi.y + bb.w;
        *(float4*)(out + (size_t)(m0 + ty * 8 + i) * H_ + n0 + tx * 4) = o;
    }
}

// ---------------- Phase 2: persistent recurrent kernel ----------------------
// 128 CTAs (1/SM): tile = 16 batch rows x 32 H cols, 256 threads.
// 8 k-groups (1 warp each, 128 k per warp); thread = 2 rows x 8 cols.
// W slice in SMEM as plain [k][32] rows; h staged row-pair-interleaved.
#define RGRID    128
#define RTHREADS 256
#define BT 16
#define NT 32
#define KSLICE 128                       // k per warp
#define HPSTR 2052                       // floats per rowpair (513*16B, odd -> conflict-free)
#define W_S_FLOATS (H_ * NT)             // 32768 floats = 128 KB
#define HP_FLOATS  (8 * HPSTR)           // 16416 floats
#define RNN_SMEM_BYTES ((W_S_FLOATS + HP_FLOATS) * 4)

__global__ void __launch_bounds__(RTHREADS, 1)
rnn_kernel(const float* __restrict__ W, float* __restrict__ out) {
    extern __shared__ float smem[];
    float* w_s  = smem;                  // [1024][32]
    float* hp_s = smem + W_S_FLOATS;     // [8 rowpairs][HPSTR]

    const int tid  = threadIdx.x;
    const int bt   = blockIdx.x >> 5;    // 0..3
    const int nt   = blockIdx.x & 31;    // 0..31
    const int b0   = bt * BT;
    const int n0   = nt * NT;

    const int lane = tid & 31;
    const int kg   = tid >> 5;           // warp id = k-group 0..7
    const int rp   = lane & 7;           // rowpair 0..7
    const int cq   = lane >> 3;          // col-octet 0..3

    // ---- one-time: copy W[:, n0:n0+32] to SMEM rows (reused 1024 steps) ----
    for (int i = tid; i < W_S_FLOATS / 4; i += RTHREADS) {
        int k  = i >> 3;
        int n4 = (i & 7) << 2;
        float4 v = *(const float4*)(W + (size_t)k * H_ + n0 + n4);
        *(float4*)&w_s[k * NT + n4] = v;
    }
    __syncthreads();

    // this thread's output element for the distributed epilogue:
    const int orow = b0 + 2 * rp + (kg >> 2);
    const int ocol = n0 + cq * 8 + (kg & 3) * 2;

    const float* wrow   = w_s + kg * KSLICE * NT + cq * 8;
    const float* hpk    = hp_s + rp * HPSTR + kg * KSLICE * 2;
    unsigned long long* red = (unsigned long long*)hp_s;  // reused after compute

    for (int t = 0; t < T_; ++t) {
        // ---- prefetch xp for this thread's output element (L1-bypass) ----
        size_t obase = ((size_t)orow * T_ + t) * H_ + ocol;
        float2 xv = __ldcg((const float2*)(out + obase));

        // ---- stage h_prev (pair-interleaved) from L2 into SMEM ----
        const float* hsrc = g_h[t & 1];
#pragma unroll
        for (int it = 0; it < 8; ++it) {
            int i  = tid + it * 256;         // 0..2047
            int p  = i >> 8;                 // rowpair
            int kc = i & 255;                // float4 chunk along k
            const float* ra = hsrc + (size_t)(b0 + 2 * p) * H_ + kc * 4;
            float4 a = __ldcg((const float4*)ra);
            float4 b = __ldcg((const float4*)(ra + H_));
            float* dst = hp_s + (size_t)p * HPSTR + kc * 8;
            *(float4*)dst       = make_float4(a.x, b.x, a.y, b.y);
            *(float4*)(dst + 4) = make_float4(a.z, b.z, a.w, b.w);
        }
        __syncthreads();

        // ---- FMA loop over this warp's 128-k slice: 2 rows x 8 cols ----
        unsigned long long ar0[4] = {0ull, 0ull, 0ull, 0ull};
        unsigned long long ar1[4] = {0ull, 0ull, 0ull, 0ull};
#pragma unroll 8
        for (int k = 0; k < KSLICE; k += 2) {
            float4 hv = *(const float4*)(hpk + k * 2);  // (r0k,r1k,r0k1,r1k1)
            ulonglong2 wa0 = *(const ulonglong2*)(wrow + k * NT);
            ulonglong2 wb0 = *(const ulonglong2*)(wrow + k * NT + 4);
            ulonglong2 wa1 = *(const ulonglong2*)(wrow + (k + 1) * NT);
            ulonglong2 wb1 = *(const ulonglong2*)(wrow + (k + 1) * NT + 4);
            unsigned long long h0  = f2dup(hv.x);
            unsigned long long h1  = f2dup(hv.y);
            unsigned long long h0b = f2dup(hv.z);
            unsigned long long h1b = f2dup(hv.w);
            ar0[0] = f2fma(h0, wa0.x, ar0[0]);
            ar0[1] = f2fma(h0, wa0.y, ar0[1]);
            ar0[2] = f2fma(h0, wb0.x, ar0[2]);
            ar0[3] = f2fma(h0, wb0.y, ar0[3]);
            ar1[0] = f2fma(h1, wa0.x, ar1[0]);
            ar1[1] = f2fma(h1, wa0.y, ar1[1]);
            ar1[2] = f2fma(h1, wb0.x, ar1[2]);
            ar1[3] = f2fma(h1, wb0.y, ar1[3]);
            ar0[0] = f2fma(h0b, wa1.x, ar0[0]);
            ar0[1] = f2fma(h0b, wa1.y, ar0[1]);
            ar0[2] = f2fma(h0b, wb1.x, ar0[2]);
            ar0[3] = f2fma(h0b, wb1.y, ar0[3]);
            ar1[0] = f2fma(h1b, wa1.x, ar1[0]);
            ar1[1] = f2fma(h1b, wa1.y, ar1[1]);
            ar1[2] = f2fma(h1b, wb1.x, ar1[2]);
            ar1[3] = f2fma(h1b, wb1.y, ar1[3]);
        }

        // ---- 8-way cross-warp reduction via SMEM (layout [kg][j][lane]) ----
        __syncthreads();                 // hp reads done -> safe to overwrite
#pragma unroll
        for (int j = 0; j < 4; ++j) {
            red[(kg * 8 + j) * 32 + lane]     = ar0[j];
            red[(kg * 8 + 4 + j) * 32 + lane] = ar1[j];
        }
        __syncthreads();

        // thread sums value j==kg of its (rp,cq) tile across all 8 k-groups
        unsigned long long s = red[(0 * 8 + kg) * 32 + lane];
#pragma unroll
        for (int ks = 1; ks < 8; ++ks)
            s = f2add(s, red[(ks * 8 + kg) * 32 + lane]);

        float2 sv = f2unpack(s);
        float2 hn;
        hn.x = tanhf(sv.x + xv.x);
        hn.y = tanhf(sv.y + xv.y);
        __stcg((float2*)(out + obase), hn);
        __stcg((float2*)(g_h[(t + 1) & 1] + (size_t)orow * H_ + ocol), hn);

        // ---- per-bt-group grid barrier (32 CTAs), release/acquire ----
        __syncthreads();
        if (tid == 0) {
            unsigned* bar = &g_bar4[bt];
            asm volatile("red.release.gpu.global.add.u32 [%0], 1;"
                         :: "l"(bar) : "memory");
            const unsigned target = 32u * (unsigned)(t + 1);
            unsigned v;
            do {
                asm volatile("ld.acquire.gpu.global.u32 %0, [%1];"
                             : "=r"(v) : "l"(bar));
            } while (v < target);
        }
        __syncthreads();
    }
}

// ---------------- launch ----------------------------------------------------
extern "C" void kernel_launch(void* const* d_in, const int* in_sizes, int n_in,
                              void* d_out, int out_size) {
    const float *x = nullptr, *hw = nullptr, *iw = nullptr, *bias = nullptr;
    for (int i = 0; i < n_in; ++i) {
        long long s = in_sizes[i];
        if      (s == (long long)B_ * T_ * I_) x    = (const float*)d_in[i];
        else if (s == (long long)H_ * H_)      hw   = (const float*)d_in[i];
        else if (s == (long long)I_ * H_)      iw   = (const float*)d_in[i];
        else if (s == (long long)H_)           bias = (const float*)d_in[i];
    }
    float* out = (float*)d_out;

    cudaFuncSetAttribute(rnn_kernel,
                         cudaFuncAttributeMaxDynamicSharedMemorySize,
                         RNN_SMEM_BYTES);

    dim3 pgrid(H_ / PTN, (B_ * T_) / PTM);   // (16, 512)
    proj_kernel<<<pgrid, 256>>>(x, iw, bias, out);
    init_kernel<<<64, 256>>>();
    rnn_kernel<<<RGRID, RTHREADS, RNN_SMEM_BYTES>>>(hw, out);
}

// round 8
// speedup vs baseline: 2.0695x; 1.0036x over previous
#include <cuda_runtime.h>
#include <cuda_bf16.h>
#include <cstdint>
#include <math.h>

#define B_  64
#define T_  1024
#define I_  512
#define H_  1024

// ===================== f32x2 helpers (proj kernel) ==========================
__device__ __forceinline__ unsigned long long f2fma(unsigned long long a,
                                                    unsigned long long b,
                                                    unsigned long long c) {
    unsigned long long d;
    asm("fma.rn.f32x2 %0, %1, %2, %3;" : "=l"(d) : "l"(a), "l"(b), "l"(c));
    return d;
}
__device__ __forceinline__ unsigned long long f2dup(float x) {
    unsigned long long d;
    asm("mov.b64 %0, {%1, %1};" : "=l"(d) : "f"(x));
    return d;
}
__device__ __forceinline__ float2 f2unpack(unsigned long long v) {
    float2 r;
    asm("mov.b64 {%0, %1}, %2;" : "=f"(r.x), "=f"(r.y) : "l"(v));
    return r;
}

// ===================== warp-mma helpers (sm_80-era, valid on sm_103) ========
__device__ __forceinline__ uint32_t smem_u32(const void* p) {
    uint32_t a;
    asm("{ .reg .u64 t; cvta.to.shared.u64 t, %1; cvt.u32.u64 %0, t; }"
        : "=r"(a) : "l"(p));
    return a;
}
__device__ __forceinline__ void ldsm4(uint32_t& r0, uint32_t& r1,
                                      uint32_t& r2, uint32_t& r3, uint32_t a) {
    asm volatile("ldmatrix.sync.aligned.m8n8.x4.shared.b16 {%0,%1,%2,%3}, [%4];"
                 : "=r"(r0), "=r"(r1), "=r"(r2), "=r"(r3) : "r"(a));
}
__device__ __forceinline__ void mma_bf16(float* c, const uint32_t* a,
                                         uint32_t b0, uint32_t b1) {
    asm volatile("mma.sync.aligned.m16n8k16.row.col.f32.bf16.bf16.f32 "
                 "{%0,%1,%2,%3}, {%4,%5,%6,%7}, {%8,%9}, {%0,%1,%2,%3};"
                 : "+f"(c[0]), "+f"(c[1]), "+f"(c[2]), "+f"(c[3])
                 : "r"(a[0]), "r"(a[1]), "r"(a[2]), "r"(a[3]),
                   "r"(b0), "r"(b1));
}

// ===================== global scratch =======================================
__device__ float    g_h[2][B_ * H_];        // hidden state, double-buffered
__device__ float    g_part[2][8][B_ * H_];  // K-group partials, double-buffered
__device__ unsigned g_gbar;                 // global 128-CTA barrier counter
__device__ unsigned g_bar2[16];             // per-ng partial-ready counters

__global__ void init_kernel() {
    int idx = blockIdx.x * blockDim.x + threadIdx.x;
    for (int i = idx; i < B_ * H_; i += gridDim.x * blockDim.x)
        g_h[0][i] = 0.0f;
    if (idx == 0) g_gbar = 0u;
    if (idx < 16) g_bar2[idx] = 0u;
}

// ===================== Phase 1: xp = x @ input_w + b ========================
#define PTM 128
#define PTN 64
#define PTK 32
#define ASTR 132
#define BSTR 68

__global__ void __launch_bounds__(256)
proj_kernel(const float* __restrict__ x, const float* __restrict__ wi,
            const float* __restrict__ bias, float* __restrict__ out) {
    __shared__ float As[PTK * ASTR];
    __shared__ float Bs[PTK * BSTR];
    const int tid = threadIdx.x;
    const int m0 = blockIdx.y * PTM;
    const int n0 = blockIdx.x * PTN;
    const int ty = tid >> 4;
    const int tx = tid & 15;

    unsigned long long acc[8][2];
#pragma unroll
    for (int i = 0; i < 8; ++i) { acc[i][0] = 0ull; acc[i][1] = 0ull; }

    for (int kt = 0; kt < I_ / PTK; ++kt) {
        const int k0 = kt * PTK;
#pragma unroll
        for (int i = 0; i < 4; ++i) {
            int idx = tid + i * 256;
            int row = idx >> 3;
            int kl  = (idx & 7) << 2;
            float4 v = *(const float4*)(x + (size_t)(m0 + row) * I_ + k0 + kl);
            As[(kl + 0) * ASTR + row] = v.x;
            As[(kl + 1) * ASTR + row] = v.y;
            As[(kl + 2) * ASTR + row] = v.z;
            As[(kl + 3) * ASTR + row] = v.w;
        }
#pragma unroll
        for (int i = 0; i < 2; ++i) {
            int idx = tid + i * 256;
            int kr  = idx >> 4;
            int c4  = (idx & 15) << 2;
            float4 v = *(const float4*)(wi + (size_t)(k0 + kr) * H_ + n0 + c4);
            *(float4*)&Bs[kr * BSTR + c4] = v;
        }
        __syncthreads();
#pragma unroll
        for (int k = 0; k < PTK; ++k) {
            float a[8];
            *(float4*)&a[0] = *(const float4*)&As[k * ASTR + ty * 8];
            *(float4*)&a[4] = *(const float4*)&As[k * ASTR + ty * 8 + 4];
            ulonglong2 bv = *(const ulonglong2*)&Bs[k * BSTR + tx * 4];
#pragma unroll
            for (int i = 0; i < 8; ++i) {
                unsigned long long ad = f2dup(a[i]);
                acc[i][0] = f2fma(ad, bv.x, acc[i][0]);
                acc[i][1] = f2fma(ad, bv.y, acc[i][1]);
            }
        }
        __syncthreads();
    }
    float4 bb = *(const float4*)(bias + n0 + tx * 4);
#pragma unroll
    for (int i = 0; i < 8; ++i) {
        float2 lo = f2unpack(acc[i][0]);
        float2 hi = f2unpack(acc[i][1]);
        float4 o;
        o.x = lo.x + bb.x; o.y = lo.y + bb.y;
        o.z = hi.x + bb.z; o.w = hi.y + bb.w;
        *(float4*)(out + (size_t)(m0 + ty * 8 + i) * H_ + n0 + tx * 4) = o;
    }
}

// ===================== Phase 2: HMMA split-bf16 recurrence ==================
// 128 CTAs = 8 k-groups x 16 n-groups. CTA: M=64 x N=64 x K=128.
// fp32 = hi + lo (bf16); D = Ahi*Whi + Ahi*Wlo + Alo*Whi in fp32 accum.
// SMEM tiles: [row][128 k] bf16, 256 B/row, XOR-swizzled (chunk ^= row&7).
#define A_HI 0
#define A_LO 16384
#define W_HI 32768
#define W_LO 49152
#define RNN_SMEM_BYTES 65536

// byte offset of element (row, k) in a [.][128] bf16 swizzled tile
__device__ __forceinline__ uint32_t tswz(int row, int k) {
    uint32_t kb = (uint32_t)(k * 2);
    return (uint32_t)(row * 256) + ((((kb >> 4) ^ (row & 7)) << 4) | (kb & 15));
}

__global__ void __launch_bounds__(256, 1)
rnn_mma_kernel(const float* __restrict__ W, float* __restrict__ out) {
    extern __shared__ char smem[];
    const uint32_t sb = smem_u32(smem);
    const int tid  = threadIdx.x;
    const int wid  = tid >> 5;
    const int lane = tid & 31;
    const int kg   = blockIdx.x >> 4;    // 0..7
    const int ng   = blockIdx.x & 15;    // 0..15
    const int ksl  = kg * 128;
    const int nsl  = ng * 64;

    // ---- build W^T hi/lo tiles once: Wt[n][k] = W[ksl+k][nsl+n] ----
    for (int q = tid; q < 64 * 128; q += 256) {
        int k = q >> 6;                  // coalesced along n
        int n = q & 63;
        float w = W[(size_t)(ksl + k) * H_ + nsl + n];
        __nv_bfloat16 hi = __float2bfloat16_rn(w);
        __nv_bfloat16 lo = __float2bfloat16_rn(w - __bfloat162float(hi));
        uint32_t off = tswz(n, k);
        *(unsigned short*)(smem + W_HI + off) = *(unsigned short*)&hi;
        *(unsigned short*)(smem + W_LO + off) = *(unsigned short*)&lo;
    }
    __syncthreads();

    // warp tile: m0 = (wid&3)*16 (M), wn = wid>>2 -> n0w = wn*32 (N)
    const int m0  = (wid & 3) * 16;
    const int n0w = (wid >> 2) * 32;
    const int lr  = lane & 15;           // ldmatrix row within 16
    const int kh  = lane >> 4;           // k-half (8 elems = 16 B)

    // per-thread ldmatrix base addresses (chunk index added per k-step)
    const uint32_t a_row_hi = sb + A_HI + (uint32_t)((m0 + lr) * 256);
    const uint32_t a_row_lo = sb + A_LO + (uint32_t)((m0 + lr) * 256);
    const uint32_t w_row0_h = sb + W_HI + (uint32_t)((n0w + lr) * 256);
    const uint32_t w_row1_h = sb + W_HI + (uint32_t)((n0w + 16 + lr) * 256);
    const uint32_t w_row0_l = sb + W_LO + (uint32_t)((n0w + lr) * 256);
    const uint32_t w_row1_l = sb + W_LO + (uint32_t)((n0w + 16 + lr) * 256);
    const uint32_t swz_a  = (uint32_t)(lane & 7);       // row&7 for A rows (lr&7)
    // chunk for k-step s: c = 2*s + kh, then ^ (row&7), <<4

    // reducer assignment: 2 output elems per thread
    const int eb = kg * 8 + (tid >> 5);
    const int en = 2 * (tid & 31);

    for (int t = 0; t < T_; ++t) {
        // ---- global barrier: all CTAs finished step t-1 ----
        if (tid == 0) {
            const unsigned tgt = 128u * (unsigned)t;
            unsigned v;
            do { asm volatile("ld.acquire.gpu.global.u32 %0, [%1];"
                              : "=r"(v) : "l"(&g_gbar)); } while (v < tgt);
        }
        __syncthreads();

        // ---- convert h[:, ksl:+128] -> A hi/lo bf16 tiles ----
        const float* hsrc = g_h[t & 1];
#pragma unroll 4
        for (int i = 0; i < 16; ++i) {
            int p   = tid + i * 256;         // 0..4095
            int row = p >> 6;                // 0..63
            int kp  = p & 63;                // k-pair
            int k   = kp * 2;
            float2 v = __ldcg((const float2*)(hsrc + (size_t)row * H_ + ksl + k));
            __nv_bfloat16 h0 = __float2bfloat16_rn(v.x);
            __nv_bfloat16 h1 = __float2bfloat16_rn(v.y);
            __nv_bfloat16 l0 = __float2bfloat16_rn(v.x - __bfloat162float(h0));
            __nv_bfloat16 l1 = __float2bfloat16_rn(v.y - __bfloat162float(h1));
            __nv_bfloat162 hp; hp.x = h0; hp.y = h1;
            __nv_bfloat162 lp; lp.x = l0; lp.y = l1;
            uint32_t off = tswz(row, k);
            *(uint32_t*)(smem + A_HI + off) = *(uint32_t*)&hp;
            *(uint32_t*)(smem + A_LO + off) = *(uint32_t*)&lp;
        }
        __syncthreads();

        // ---- mma mainloop: K=128 in 8 steps of k16, 3 split products ----
        float c[4][4];
#pragma unroll
        for (int j = 0; j < 4; ++j)
            c[j][0] = c[j][1] = c[j][2] = c[j][3] = 0.f;

#pragma unroll
        for (int s = 0; s < 8; ++s) {
            const uint32_t ca = (uint32_t)(((2 * s + kh) ^ swz_a) << 4);
            const uint32_t cw0 = (uint32_t)(((2 * s + kh) ^ (lr & 7)) << 4);
            uint32_t ah[4], al[4], bh0, bh1, bh2, bh3, bl0, bl1, bl2, bl3;
            uint32_t x0, x1, x2, x3;
            ldsm4(ah[0], ah[1], ah[2], ah[3], a_row_hi + ca);
            ldsm4(al[0], al[1], al[2], al[3], a_row_lo + ca);
            // W hi: n-tiles 0,1 then 2,3
            ldsm4(x0, x1, x2, x3, w_row0_h + cw0);
            bh0 = x0; bh1 = x2;              // ntile0 frag {b0,b1}
            uint32_t bh0b = x1, bh1b = x3;   // ntile1
            ldsm4(x0, x1, x2, x3, w_row1_h + cw0);
            bh2 = x0; bh3 = x2;              // ntile2
            uint32_t bh2b = x1, bh3b = x3;   // ntile3
            ldsm4(x0, x1, x2, x3, w_row0_l + cw0);
            bl0 = x0; bl1 = x2;
            uint32_t bl0b = x1, bl1b = x3;
            ldsm4(x0, x1, x2, x3, w_row1_l + cw0);
            bl2 = x0; bl3 = x2;
            uint32_t bl2b = x1, bl3b = x3;

            mma_bf16(c[0], ah, bh0, bh1);
            mma_bf16(c[1], ah, bh0b, bh1b);
            mma_bf16(c[2], ah, bh2, bh3);
            mma_bf16(c[3], ah, bh2b, bh3b);
            mma_bf16(c[0], ah, bl0, bl1);
            mma_bf16(c[1], ah, bl0b, bl1b);
            mma_bf16(c[2], ah, bl2, bl3);
            mma_bf16(c[3], ah, bl2b, bl3b);
            mma_bf16(c[0], al, bh0, bh1);
            mma_bf16(c[1], al, bh0b, bh1b);
            mma_bf16(c[2], al, bh2, bh3);
            mma_bf16(c[3], al, bh2b, bh3b);
        }

        // ---- store partials to global (bypass L1) ----
        {
            const int pr = t & 1;
            const int ra = m0 + (lane >> 2);
            const int rb = ra + 8;
            float* pa = &g_part[pr][kg][(size_t)ra * H_ + nsl + n0w + 2 * (lane & 3)];
            float* pb = &g_part[pr][kg][(size_t)rb * H_ + nsl + n0w + 2 * (lane & 3)];
#pragma unroll
            for (int j = 0; j < 4; ++j) {
                __stcg((float2*)(pa + j * 8), make_float2(c[j][0], c[j][1]));
                __stcg((float2*)(pb + j * 8), make_float2(c[j][2], c[j][3]));
            }
        }
        __syncthreads();
        if (tid == 0)
            asm volatile("red.release.gpu.global.add.u32 [%0], 1;"
                         :: "l"(&g_bar2[ng]) : "memory");

        // ---- wait all 8 k-groups of this n-group ----
        if (tid == 0) {
            const unsigned tgt = 8u * (unsigned)(t + 1);
            unsigned v;
            do { asm volatile("ld.acquire.gpu.global.u32 %0, [%1];"
                              : "=r"(v) : "l"(&g_bar2[ng])); } while (v < tgt);
        }
        __syncthreads();

        // ---- reduce 8 partials, add xp, tanh, write h & out ----
        {
            const int pr = t & 1;
            float2 s = make_float2(0.f, 0.f);
#pragma unroll
            for (int k2 = 0; k2 < 8; ++k2) {
                float2 pv = __ldcg((const float2*)(&g_part[pr][k2][(size_t)eb * H_ + nsl + en]));
                s.x += pv.x; s.y += pv.y;
            }
            size_t obase = ((size_t)eb * T_ + t) * H_ + nsl + en;
            float2 xv = __ldcg((const float2*)(out + obase));
            float2 hn;
            hn.x = tanhf(s.x + xv.x);
            hn.y = tanhf(s.y + xv.y);
            __stcg((float2*)(out + obase), hn);
            __stcg((float2*)(g_h[(t + 1) & 1] + (size_t)eb * H_ + nsl + en), hn);
        }
        __syncthreads();
        if (tid == 0)
            asm volatile("red.release.gpu.global.add.u32 [%0], 1;"
                         :: "l"(&g_gbar) : "memory");
    }
}

// ===================== launch ===============================================
extern "C" void kernel_launch(void* const* d_in, const int* in_sizes, int n_in,
                              void* d_out, int out_size) {
    const float *x = nullptr, *hw = nullptr, *iw = nullptr, *bias = nullptr;
    for (int i = 0; i < n_in; ++i) {
        long long s = in_sizes[i];
        if      (s == (long long)B_ * T_ * I_) x    = (const float*)d_in[i];
        else if (s == (long long)H_ * H_)      hw   = (const float*)d_in[i];
        else if (s == (long long)I_ * H_)      iw   = (const float*)d_in[i];
        else if (s == (long long)H_)           bias = (const float*)d_in[i];
    }
    float* out = (float*)d_out;

    cudaFuncSetAttribute(rnn_mma_kernel,
                         cudaFuncAttributeMaxDynamicSharedMemorySize,
                         RNN_SMEM_BYTES);

    dim3 pgrid(H_ / PTN, (B_ * T_) / PTM);   // (16, 512)
    proj_kernel<<<pgrid, 256>>>(x, iw, bias, out);
    init_kernel<<<64, 256>>>();
    rnn_mma_kernel<<<128, 256, RNN_SMEM_BYTES>>>(hw, out);
}